// round 15
// baseline (speedup 1.0000x reference)
#include <cuda_runtime.h>
#include <cstdint>

// Problem constants (fixed by the dataset)
#define K3           27
#define C            32           // C_IN == C_OUT == 32
#define PAIRS_PER_K  131072
#define N_VOX        262144

#define THREADS      128
#define TILE         128                          // pairs per tile
#define NT           8                            // tiles per block
#define BLOCKS_X     (PAIRS_PER_K / (TILE * NT))  // 128

typedef unsigned long long ull;

__device__ __forceinline__ void red_add_v4(float* p, float4 v) {
    asm volatile("red.global.add.v4.f32 [%0], {%1,%2,%3,%4};"
                 :: "l"(p), "f"(v.x), "f"(v.y), "f"(v.z), "f"(v.w) : "memory");
}
__device__ __forceinline__ void fma2(ull& d, ull a, ull b) {
    asm("fma.rn.f32x2 %0, %1, %2, %0;" : "+l"(d) : "l"(a), "l"(b));
}
__device__ __forceinline__ ull splat2(float x) {
    ull r; asm("mov.b64 %0, {%1, %1};" : "=l"(r) : "f"(x)); return r;
}
__device__ __forceinline__ void cp_async16(unsigned int dst_smem, const void* src) {
    asm volatile("cp.async.cg.shared.global [%0], [%1], 16;"
                 :: "r"(dst_smem), "l"(src) : "memory");
}

__global__ void init_bias_kernel(float* __restrict__ out,
                                 const float* __restrict__ bias) {
    int idx = blockIdx.x * blockDim.x + threadIdx.x;
    if (idx < N_VOX * (C / 4)) {
        float4 b = __ldg(((const float4*)bias) + (idx & (C / 4 - 1)));
        ((float4*)out)[idx] = b;
    }
}

// Thread (og = t&3, pg = t>>2) owns pairs pg*4..pg*4+3 and outputs 8og..8og+7.
// Swizzle key for A/O tiles: (row>>2)&7 — 8 distinct keys across the 8
// pair-groups of a warp -> 1-phase LDS.128 in the GEMM inner loop.
__global__ void __launch_bounds__(THREADS)
conv_rt_kernel(const float* __restrict__ in_feature,
               const float* __restrict__ kern,
               const int*   __restrict__ nbmap,
               float* __restrict__ out) {
    __shared__ float Ws[C * C];          // W[k][ch][o], row = input channel (4KB)
    __shared__ int2  nbs[TILE];          // (in,out) rows for current tile (1KB)
    __shared__ float At[TILE * C];       // gathered A, swizzled (16KB)
    __shared__ float Ot[TILE * C];       // acc staging, swizzled (16KB)

    const int t  = threadIdx.x;
    const int og = t & 3;
    const int pg = t >> 2;
    const int k  = blockIdx.y;
    const long kbase = (long)k * PAIRS_PER_K + (long)blockIdx.x * (TILE * NT);

    // ---- stage W[k] once per block ----
    {
        const float4* wk = (const float4*)(kern + (long)k * C * C);
        ((float4*)Ws)[t]       = __ldg(wk + t);
        ((float4*)Ws)[t + 128] = __ldg(wk + t + 128);
    }

    for (int tile = 0; tile < NT; ++tile) {
        // ---- stage nbmap (128 int2 = 64 int4) ----
        if (t < 64) {
            ((int4*)nbs)[t] =
                __ldg(((const int4*)nbmap) + ((kbase + (long)tile * TILE) >> 1) + t);
        }
        __syncthreads();

        // ---- coalesced gather via cp.async: 8 lanes per 128B input row ----
        #pragma unroll
        for (int it = 0; it < 8; ++it) {
            const int row = it * 16 + (t >> 3);
            const int cg  = t & 7;
            const int inrow = nbs[row].x;
            const float* src = in_feature + (long)inrow * C + cg * 4;
            unsigned int dst = (unsigned int)__cvta_generic_to_shared(
                At + row * C + ((cg ^ ((row >> 2) & 7)) * 4));
            cp_async16(dst, src);
        }
        asm volatile("cp.async.commit_group;" ::: "memory");
        asm volatile("cp.async.wait_group 0;" ::: "memory");
        __syncthreads();

        // ---- register GEMM: 4 pairs x 8 outs per thread ----
        ull acc[4][4];
        #pragma unroll
        for (int i = 0; i < 4; ++i)
            #pragma unroll
            for (int j = 0; j < 4; ++j) acc[i][j] = 0ULL;

        const int key = pg & 7;
        #pragma unroll
        for (int c4 = 0; c4 < 8; ++c4) {
            // A fragments: channels 4c4..4c4+3 of my 4 pair rows (1-phase LDS.128)
            float av[4][4];
            #pragma unroll
            for (int i = 0; i < 4; ++i) {
                const float4 a =
                    *(const float4*)(At + (pg * 4 + i) * C + ((c4 ^ key) * 4));
                av[i][0] = a.x; av[i][1] = a.y; av[i][2] = a.z; av[i][3] = a.w;
            }
            #pragma unroll
            for (int cc = 0; cc < 4; ++cc) {
                const int ch = c4 * 4 + cc;
                // W[ch][8og..8og+7] as 4 packed f32x2 (two 16B loads, 64B/warp)
                const ulonglong2 w01 = *(const ulonglong2*)(Ws + ch * C + og * 8);
                const ulonglong2 w23 = *(const ulonglong2*)(Ws + ch * C + og * 8 + 4);
                #pragma unroll
                for (int i = 0; i < 4; ++i) {
                    const ull a2 = splat2(av[i][cc]);
                    fma2(acc[i][0], a2, w01.x);
                    fma2(acc[i][1], a2, w01.y);
                    fma2(acc[i][2], a2, w23.x);
                    fma2(acc[i][3], a2, w23.y);
                }
            }
        }

        // ---- accs -> Ot (same swizzle key; disjoint regions, no pre-sync) ----
        #pragma unroll
        for (int i = 0; i < 4; ++i) {
            float* orp = Ot + (pg * 4 + i) * C;
            *(ulonglong2*)(orp + (((og * 2)     ^ key) * 4)) =
                make_ulonglong2(acc[i][0], acc[i][1]);
            *(ulonglong2*)(orp + (((og * 2 + 1) ^ key) * 4)) =
                make_ulonglong2(acc[i][2], acc[i][3]);
        }
        __syncthreads();

        // ---- coalesced scatter-add: 8 lanes per 128B output row ----
        #pragma unroll
        for (int it = 0; it < 8; ++it) {
            const int row = it * 16 + (t >> 3);
            const int cg  = t & 7;
            const float4 v =
                *(const float4*)(Ot + row * C + ((cg ^ ((row >> 2) & 7)) * 4));
            red_add_v4(out + (long)nbs[row].y * C + cg * 4, v);
        }
        __syncthreads();   // nbs/At reused next tile
    }
}

extern "C" void kernel_launch(void* const* d_in, const int* in_sizes, int n_in,
                              void* d_out, int out_size) {
    const float* in_feature = (const float*)d_in[0];
    const float* kern       = (const float*)d_in[1];
    const float* bias       = (const float*)d_in[2];
    const int*   nbmap      = (const int*)d_in[3];
    float* out = (float*)d_out;

    {
        int total_f4 = N_VOX * (C / 4);
        int blocks = (total_f4 + 255) / 256;
        init_bias_kernel<<<blocks, 256>>>(out, bias);
    }
    {
        dim3 grid(BLOCKS_X, K3);
        conv_rt_kernel<<<grid, THREADS>>>(in_feature, kern, nbmap, out);
    }
}